// round 6
// baseline (speedup 1.0000x reference)
#include <cuda_runtime.h>

#define NN 100000
#define EE 1600000
#define DD 64

// ---------------- scratch (static device globals; no allocation) ------------
__device__ float g_wbar[DD];
__device__ float g_bmean;
__device__ int   g_is64;
__device__ float g_snode[NN];
__device__ int   g_deg[NN];
__device__ int   g_off[NN + 1];
__device__ int   g_cur[NN];
__device__ int   g_srcRow[EE];
__device__ float g_escore[EE];
__device__ float g_agg[(size_t)NN * DD];

// ---------------- edge-index format detection -------------------------------
// Reference requests int64, but vanilla JAX (x64 disabled) silently produces
// int32. Detect on-device: if the array is int64 (little-endian, values >= 0),
// every odd 32-bit word of the leading elements is 0. Genuine int32 data there
// would be random node ids — probability of 4096 zeros is nil.
__global__ void k_detect(const unsigned* __restrict__ ei32) {
    __shared__ int any;
    int t = threadIdx.x;
    if (t == 0) any = 0;
    __syncthreads();
    int v = 0;
    for (int i = t; i < 4096; i += blockDim.x) v |= (int)ei32[2 * i + 1];
    if (v) atomicOr(&any, 1);
    __syncthreads();
    if (t == 0) g_is64 = any ? 0 : 1;
}

__device__ __forceinline__ int load_idx(const void* ei, long long pos) {
    if (g_is64) return (int)((const long long*)ei)[pos];
    return ((const int*)ei)[pos];
}

// ---------------- K0: zero degree + fold Wm/bm into score vector ------------
__global__ void k_init(const float* __restrict__ Wm, const float* __restrict__ bm) {
    int t = blockIdx.x * blockDim.x + threadIdx.x;
    if (t < NN) g_deg[t] = 0;
    if (t < DD) {
        float s = 0.f;
#pragma unroll
        for (int j = 0; j < DD; j++) s += Wm[t * DD + j];
        g_wbar[t] = s * (1.0f / DD);
        if (t == 0) {
            float b = 0.f;
            for (int j = 0; j < DD; j++) b += bm[j];
            g_bmean = b * (1.0f / DD);
        }
    }
}

// ---------------- K1: per-node score s = BETA*(x[n].wbar + bmean) -----------
__global__ void __launch_bounds__(256) k_snode(const float* __restrict__ x) {
    __shared__ float swb[DD];
    __shared__ float sbm;
    if (threadIdx.x < DD) swb[threadIdx.x] = g_wbar[threadIdx.x];
    if (threadIdx.x == 0) sbm = g_bmean;
    __syncthreads();
    int n = blockIdx.x * blockDim.x + threadIdx.x;
    if (n < NN) {
        const float4* xp = (const float4*)(x + (size_t)n * DD);
        float s = 0.f;
#pragma unroll
        for (int i = 0; i < DD / 4; i++) {
            float4 v = __ldg(&xp[i]);
            s += v.x * swb[4 * i] + v.y * swb[4 * i + 1] + v.z * swb[4 * i + 2] + v.w * swb[4 * i + 3];
        }
        g_snode[n] = s + sbm;  // BETA = 1.0
    }
}

// ---------------- K2: in-degree histogram -----------------------------------
__global__ void k_deg(const void* __restrict__ ei) {
    int e = blockIdx.x * blockDim.x + threadIdx.x;
    if (e < EE) {
        int col = load_idx(ei, (long long)EE + e);
        atomicAdd(&g_deg[col], 1);
    }
}

// ---------------- K3: exclusive scan over degrees (single block) ------------
__global__ void k_scan() {
    const int T = 1024;
    int t = threadIdx.x;
    const int chunk = (NN + T - 1) / T;
    int b = t * chunk;
    int e = b + chunk;
    if (b > NN) b = NN;
    if (e > NN) e = NN;
    int sum = 0;
    for (int i = b; i < e; i++) sum += g_deg[i];
    __shared__ int sh[T];
    sh[t] = sum;
    __syncthreads();
    for (int off = 1; off < T; off <<= 1) {
        int v = (t >= off) ? sh[t - off] : 0;
        __syncthreads();
        sh[t] += v;
        __syncthreads();
    }
    int run = sh[t] - sum;  // exclusive prefix
    for (int i = b; i < e; i++) {
        g_off[i] = run;
        g_cur[i] = run;
        run += g_deg[i];
    }
    if (t == T - 1) g_off[NN] = run;  // == EE
}

// ---------------- K4: scatter edges into CSR-by-destination -----------------
__global__ void k_scatter(const void* __restrict__ ei) {
    int e = blockIdx.x * blockDim.x + threadIdx.x;
    if (e < EE) {
        int row = load_idx(ei, e);
        int col = load_idx(ei, (long long)EE + e);
        int pos = atomicAdd(&g_cur[col], 1);
        g_srcRow[pos] = row;
        g_escore[pos] = g_snode[row];
    }
}

// ---------------- K5: warp-per-node softmax aggregation (atomic-free) -------
// agg[n] = sum_e softmax_weight(e) * x[src(e)]
__global__ void __launch_bounds__(256) k_agg(const float* __restrict__ x) {
    int warp = (blockIdx.x * blockDim.x + threadIdx.x) >> 5;
    int lane = threadIdx.x & 31;
    if (warp >= NN) return;
    int n = warp;
    int beg = g_off[n], end = g_off[n + 1];

    // pass 1: max score (numerical stability)
    float m = -1e30f;
    for (int i = beg + lane; i < end; i += 32) m = fmaxf(m, g_escore[i]);
#pragma unroll
    for (int o = 16; o; o >>= 1) m = fmaxf(m, __shfl_xor_sync(0xffffffffu, m, o));

    // pass 2: weighted accumulation. 2 edge slots x 16 lanes x float4.
    int half = lane >> 4;   // edge slot
    int q = lane & 15;      // dim quarter (4 floats)
    float4 acc = make_float4(0.f, 0.f, 0.f, 0.f);
    float sumw = 0.f;
    for (int i = beg + half; i < end; i += 2) {
        float w = __expf(g_escore[i] - m);
        if (q == 0) sumw += w;
        const float4* xp = (const float4*)(x + (size_t)g_srcRow[i] * DD);
        float4 v = __ldg(&xp[q]);
        acc.x += w * v.x; acc.y += w * v.y; acc.z += w * v.z; acc.w += w * v.w;
    }
    // combine the two edge slots
    acc.x += __shfl_xor_sync(0xffffffffu, acc.x, 16);
    acc.y += __shfl_xor_sync(0xffffffffu, acc.y, 16);
    acc.z += __shfl_xor_sync(0xffffffffu, acc.z, 16);
    acc.w += __shfl_xor_sync(0xffffffffu, acc.w, 16);
#pragma unroll
    for (int o = 16; o; o >>= 1) sumw += __shfl_xor_sync(0xffffffffu, sumw, o);

    float inv = (sumw > 0.f) ? (1.0f / sumw) : 0.f;
    if (half == 0) {
        float4 r = make_float4(acc.x * inv, acc.y * inv, acc.z * inv, acc.w * inv);
        ((float4*)(g_agg + (size_t)n * DD))[q] = r;
    }
}

// ---------------- K6: out = agg@Wm + 1[deg>0]*bm + x@Wr + br ----------------
// Fused K=128 GEMM over concatenated [agg | x] rows against [[Wm];[Wr]].
__global__ void __launch_bounds__(256) k_out(
    const float* __restrict__ x,
    const float* __restrict__ Wm, const float* __restrict__ bm,
    const float* __restrict__ Wr, const float* __restrict__ br,
    float* __restrict__ out) {
    __shared__ float sW[128 * 64];   // [k][j]
    __shared__ float sA[16 * 128];   // [node][k]  (k<64: agg, k>=64: x)
    __shared__ float sBr[64], sBm[64];
    __shared__ float sHas[16];
    int t = threadIdx.x;
    for (int i = t; i < 4096; i += 256) {
        sW[i] = Wm[i];
        sW[4096 + i] = Wr[i];
    }
    if (t < 64) { sBr[t] = br[t]; sBm[t] = bm[t]; }
    __syncthreads();

    int j = t & 63;   // output column
    int g = t >> 6;   // node group (4 nodes each)
    const int NTILES = NN / 16;  // 6250 exact
    for (int tile = blockIdx.x; tile < NTILES; tile += gridDim.x) {
        int n0 = tile * 16;
        for (int i = t; i < 16 * 64; i += 256) {
            int node = i >> 6, k = i & 63;
            sA[node * 128 + k]      = g_agg[(size_t)(n0 + node) * DD + k];
            sA[node * 128 + 64 + k] = x[(size_t)(n0 + node) * DD + k];
        }
        if (t < 16) sHas[t] = (g_off[n0 + t + 1] > g_off[n0 + t]) ? 1.0f : 0.0f;
        __syncthreads();

        const float* A0 = &sA[(g * 4 + 0) * 128];
        const float* A1 = &sA[(g * 4 + 1) * 128];
        const float* A2 = &sA[(g * 4 + 2) * 128];
        const float* A3 = &sA[(g * 4 + 3) * 128];
        float a0 = 0.f, a1 = 0.f, a2 = 0.f, a3 = 0.f;
#pragma unroll 8
        for (int k = 0; k < 128; k += 4) {
            float w0 = sW[(k + 0) * 64 + j];
            float w1 = sW[(k + 1) * 64 + j];
            float w2 = sW[(k + 2) * 64 + j];
            float w3 = sW[(k + 3) * 64 + j];
            float4 v0 = *(const float4*)(A0 + k);
            float4 v1 = *(const float4*)(A1 + k);
            float4 v2 = *(const float4*)(A2 + k);
            float4 v3 = *(const float4*)(A3 + k);
            a0 += w0 * v0.x + w1 * v0.y + w2 * v0.z + w3 * v0.w;
            a1 += w0 * v1.x + w1 * v1.y + w2 * v1.z + w3 * v1.w;
            a2 += w0 * v2.x + w1 * v2.y + w2 * v2.z + w3 * v2.w;
            a3 += w0 * v3.x + w1 * v3.y + w2 * v3.z + w3 * v3.w;
        }
        int nb = n0 + g * 4;
        out[(size_t)(nb + 0) * DD + j] = a0 + sHas[g * 4 + 0] * sBm[j] + sBr[j];
        out[(size_t)(nb + 1) * DD + j] = a1 + sHas[g * 4 + 1] * sBm[j] + sBr[j];
        out[(size_t)(nb + 2) * DD + j] = a2 + sHas[g * 4 + 2] * sBm[j] + sBr[j];
        out[(size_t)(nb + 3) * DD + j] = a3 + sHas[g * 4 + 3] * sBm[j] + sBr[j];
        __syncthreads();
    }
}

// ---------------- launcher ---------------------------------------------------
extern "C" void kernel_launch(void* const* d_in, const int* in_sizes, int n_in,
                              void* d_out, int out_size) {
    const float* x  = (const float*)d_in[0];
    const void*  ei = d_in[1];
    const float* Wm = (const float*)d_in[2];
    const float* bm = (const float*)d_in[3];
    const float* Wr = (const float*)d_in[4];
    const float* br = (const float*)d_in[5];
    float* out = (float*)d_out;

    k_detect<<<1, 256>>>((const unsigned*)ei);
    k_init<<<(NN + 255) / 256, 256>>>(Wm, bm);
    k_snode<<<(NN + 255) / 256, 256>>>(x);
    k_deg<<<(EE + 255) / 256, 256>>>(ei);
    k_scan<<<1, 1024>>>();
    k_scatter<<<(EE + 255) / 256, 256>>>(ei);
    k_agg<<<(NN + 7) / 8, 256>>>(x);
    k_out<<<2048, 256>>>(x, Wm, bm, Wr, br, out);
}

// round 7
// speedup vs baseline: 1.1621x; 1.1621x over previous
#include <cuda_runtime.h>

#define NN 100000
#define EE 1600000
#define DD 64

// ---------------- scratch (static device globals; no allocation) ------------
__device__ float    g_wbar[DD];
__device__ float    g_bmean;
__device__ int      g_is64;
__device__ unsigned g_smaxkey;
__device__ float    g_smaxf;
__device__ float    g_snode[NN];
__device__ float    g_has[NN];
__device__ int      g_deg[NN];
__device__ int      g_off[NN + 1];
__device__ int      g_cur[NN];
__device__ int      g_row32[EE];
__device__ int      g_col32[EE];
__device__ int2     g_edge[EE];          // .x = srcRow, .y = bits(exp(s - gmax))
__device__ float    g_agg[(size_t)NN * DD];

// ---------------- packed f32x2 FMA (2x fp32 FMA rate on sm_103a) ------------
union F2U { float2 f2; unsigned long long u; };
__device__ __forceinline__ F2U ffma2(F2U a, F2U b, F2U c) {
    F2U d;
    asm("fma.rn.f32x2 %0, %1, %2, %3;" : "=l"(d.u) : "l"(a.u), "l"(b.u), "l"(c.u));
    return d;
}

// ---------------- edge-index format detection -------------------------------
// int64 little-endian non-negative ids => every odd 32-bit word of the leading
// elements is 0. Genuine int32 data there would be random node ids.
__global__ void k_detect(const unsigned* __restrict__ ei32) {
    __shared__ int any;
    int t = threadIdx.x;
    if (t == 0) any = 0;
    __syncthreads();
    int v = 0;
    for (int i = t; i < 4096; i += blockDim.x) v |= (int)ei32[2 * i + 1];
    if (v) atomicOr(&any, 1);
    __syncthreads();
    if (t == 0) g_is64 = any ? 0 : 1;
}

__device__ __forceinline__ int load_idx(const void* ei, long long pos) {
    if (g_is64) return (int)((const long long*)ei)[pos];
    return ((const int*)ei)[pos];
}

// ---------------- K0: zero deg + fold Wm/bm into score vector ---------------
__global__ void k_init(const float* __restrict__ Wm, const float* __restrict__ bm) {
    int t = blockIdx.x * blockDim.x + threadIdx.x;
    if (t < NN) g_deg[t] = 0;
    if (t == 0) g_smaxkey = 0u;
    if (t < DD) {
        float s = 0.f;
#pragma unroll
        for (int j = 0; j < DD; j++) s += Wm[t * DD + j];
        g_wbar[t] = s * (1.0f / DD);
        if (t == 0) {
            float b = 0.f;
            for (int j = 0; j < DD; j++) b += bm[j];
            g_bmean = b * (1.0f / DD);
        }
    }
}

// ---------------- K1: per-node score + global max (monotone-uint) -----------
__global__ void __launch_bounds__(256) k_snode(const float* __restrict__ x) {
    __shared__ float swb[DD];
    __shared__ float sbm;
    if (threadIdx.x < DD) swb[threadIdx.x] = g_wbar[threadIdx.x];
    if (threadIdx.x == 0) sbm = g_bmean;
    __syncthreads();
    int n = blockIdx.x * blockDim.x + threadIdx.x;
    float s = -1e30f;
    if (n < NN) {
        const float4* xp = (const float4*)(x + (size_t)n * DD);
        float acc = 0.f;
#pragma unroll
        for (int i = 0; i < DD / 4; i++) {
            float4 v = __ldg(&xp[i]);
            acc += v.x * swb[4 * i] + v.y * swb[4 * i + 1] + v.z * swb[4 * i + 2] + v.w * swb[4 * i + 3];
        }
        s = acc + sbm;  // BETA = 1.0
        g_snode[n] = s;
    }
    float m = s;
#pragma unroll
    for (int o = 16; o; o >>= 1) m = fmaxf(m, __shfl_xor_sync(0xffffffffu, m, o));
    if ((threadIdx.x & 31) == 0) {
        unsigned b = __float_as_uint(m);
        unsigned key = (b & 0x80000000u) ? ~b : (b | 0x80000000u);
        atomicMax(&g_smaxkey, key);
    }
}

// ---------------- K2: degree histogram + index conversion to int32 ----------
__global__ void k_deg(const void* __restrict__ ei) {
    int e = blockIdx.x * blockDim.x + threadIdx.x;
    if (e < EE) {
        int row = load_idx(ei, e);
        int col = load_idx(ei, (long long)EE + e);
        g_row32[e] = row;
        g_col32[e] = col;
        atomicAdd(&g_deg[col], 1);
    }
}

// ---------------- K3: exclusive scan over degrees (single block) ------------
__global__ void k_scan() {
    const int T = 1024;
    int t = threadIdx.x;
    if (t == 0) {
        unsigned k = g_smaxkey;
        unsigned b = (k & 0x80000000u) ? (k ^ 0x80000000u) : ~k;
        g_smaxf = __uint_as_float(b);
    }
    const int chunk = (NN + T - 1) / T;
    int b = t * chunk;
    int e = b + chunk;
    if (b > NN) b = NN;
    if (e > NN) e = NN;
    int sum = 0;
    for (int i = b; i < e; i++) sum += g_deg[i];
    __shared__ int sh[T];
    sh[t] = sum;
    __syncthreads();
    for (int off = 1; off < T; off <<= 1) {
        int v = (t >= off) ? sh[t - off] : 0;
        __syncthreads();
        sh[t] += v;
        __syncthreads();
    }
    int run = sh[t] - sum;  // exclusive prefix
    for (int i = b; i < e; i++) {
        g_off[i] = run;
        g_cur[i] = run;
        run += g_deg[i];
    }
    if (t == T - 1) g_off[NN] = run;  // == EE
}

// ---------------- K4: scatter (row, exp-weight) into CSR-by-dest ------------
__global__ void k_scatter() {
    int e = blockIdx.x * blockDim.x + threadIdx.x;
    if (e < EE) {
        int row = g_row32[e];
        int col = g_col32[e];
        float w = __expf(g_snode[row] - g_smaxf);
        int pos = atomicAdd(&g_cur[col], 1);
        g_edge[pos] = make_int2(row, __float_as_int(w));
    }
}

// ---------------- K5: warp-per-node weighted aggregation (single pass) ------
__global__ void __launch_bounds__(256) k_agg(const float* __restrict__ x) {
    int warp = (blockIdx.x * blockDim.x + threadIdx.x) >> 5;
    int lane = threadIdx.x & 31;
    if (warp >= NN) return;
    int n = warp;
    int beg = g_off[n], end = g_off[n + 1];

    int half = lane >> 4;   // edge slot (2 edges in flight)
    int q = lane & 15;      // dim quarter (float4)
    float4 acc = make_float4(0.f, 0.f, 0.f, 0.f);
    float sumw = 0.f;
#pragma unroll 2
    for (int i = beg + half; i < end; i += 2) {
        int2 ed = __ldg(&g_edge[i]);
        float w = __int_as_float(ed.y);
        if (q == 0) sumw += w;
        const float4* xp = (const float4*)(x + (size_t)ed.x * DD);
        float4 v = __ldg(&xp[q]);
        acc.x += w * v.x; acc.y += w * v.y; acc.z += w * v.z; acc.w += w * v.w;
    }
    acc.x += __shfl_xor_sync(0xffffffffu, acc.x, 16);
    acc.y += __shfl_xor_sync(0xffffffffu, acc.y, 16);
    acc.z += __shfl_xor_sync(0xffffffffu, acc.z, 16);
    acc.w += __shfl_xor_sync(0xffffffffu, acc.w, 16);
#pragma unroll
    for (int o = 16; o; o >>= 1) sumw += __shfl_xor_sync(0xffffffffu, sumw, o);

    float inv = (sumw > 0.f) ? (1.0f / sumw) : 0.f;
    if (half == 0) {
        float4 r = make_float4(acc.x * inv, acc.y * inv, acc.z * inv, acc.w * inv);
        ((float4*)(g_agg + (size_t)n * DD))[q] = r;
    }
    if (lane == 0) g_has[n] = (sumw > 0.f) ? 1.0f : 0.0f;
}

// ---------------- K6: out = agg@Wm + has*bm + x@Wr + br ---------------------
// 256 nodes x 64 cols per block; thread = 8 nodes x 8 cols, f32x2 FMAs.
#define SA_STRIDE 260  // 16B-aligned row stride (260*4 bytes), conflict-free
__global__ void __launch_bounds__(256, 1) k_out(
    const float* __restrict__ x,
    const float* __restrict__ Wm, const float* __restrict__ bm,
    const float* __restrict__ Wr, const float* __restrict__ br,
    float* __restrict__ out) {
    __shared__ float sAk[32 * SA_STRIDE];  // [k within chunk][node] k-major
    __shared__ float sWs[32 * 64];         // [k within chunk][col]

    int t = threadIdx.x;
    int cg = t & 7;        // col group: cols cg*8 .. cg*8+7
    int ng = t >> 3;       // node group: nodes ng*8 .. ng*8+7 (0..31)
    int nb0 = blockIdx.x * 256;

    float4 bm0 = __ldg((const float4*)(bm + cg * 8));
    float4 bm1 = __ldg((const float4*)(bm + cg * 8 + 4));
    float4 br0 = __ldg((const float4*)(br + cg * 8));
    float4 br1 = __ldg((const float4*)(br + cg * 8 + 4));

    F2U acc[8][4];
#pragma unroll
    for (int i = 0; i < 8; i++)
#pragma unroll
        for (int p = 0; p < 4; p++) acc[i][p].u = 0ull;

    int node = nb0 + t;  // loader: this thread stages row `node`
    for (int kc = 0; kc < 4; kc++) {
        const float* Asrc = (kc < 2) ? g_agg : x;
        int koff = (kc < 2) ? kc * 32 : (kc - 2) * 32;
        const float* Wsrc = (kc < 2) ? (Wm + kc * 32 * 64) : (Wr + (kc - 2) * 32 * 64);
        __syncthreads();
        // stage A chunk (transpose to k-major): thread reads its node's 128B
        const float4* ap = (const float4*)(Asrc + (size_t)node * DD + koff);
#pragma unroll
        for (int kq = 0; kq < 8; kq++) {
            float4 v = (node < NN) ? __ldg(&ap[kq]) : make_float4(0.f, 0.f, 0.f, 0.f);
            sAk[(kq * 4 + 0) * SA_STRIDE + t] = v.x;
            sAk[(kq * 4 + 1) * SA_STRIDE + t] = v.y;
            sAk[(kq * 4 + 2) * SA_STRIDE + t] = v.z;
            sAk[(kq * 4 + 3) * SA_STRIDE + t] = v.w;
        }
        // stage W chunk (straight copy)
        ((float4*)sWs)[t] = __ldg(&((const float4*)Wsrc)[t]);
        ((float4*)sWs)[t + 256] = __ldg(&((const float4*)Wsrc)[t + 256]);
        __syncthreads();

#pragma unroll 4
        for (int kk = 0; kk < 32; kk++) {
            float4 wa = *(const float4*)&sWs[kk * 64 + cg * 8];
            float4 wb = *(const float4*)&sWs[kk * 64 + cg * 8 + 4];
            F2U w0, w1, w2, w3;
            w0.f2 = make_float2(wa.x, wa.y); w1.f2 = make_float2(wa.z, wa.w);
            w2.f2 = make_float2(wb.x, wb.y); w3.f2 = make_float2(wb.z, wb.w);
            float4 a03 = *(const float4*)&sAk[kk * SA_STRIDE + ng * 8];
            float4 a47 = *(const float4*)&sAk[kk * SA_STRIDE + ng * 8 + 4];
            float av[8] = {a03.x, a03.y, a03.z, a03.w, a47.x, a47.y, a47.z, a47.w};
#pragma unroll
            for (int i = 0; i < 8; i++) {
                F2U ap2; ap2.f2 = make_float2(av[i], av[i]);
                acc[i][0] = ffma2(ap2, w0, acc[i][0]);
                acc[i][1] = ffma2(ap2, w1, acc[i][1]);
                acc[i][2] = ffma2(ap2, w2, acc[i][2]);
                acc[i][3] = ffma2(ap2, w3, acc[i][3]);
            }
        }
    }

    // epilogue: + has*bm + br, store 8 nodes x 8 cols
#pragma unroll
    for (int i = 0; i < 8; i++) {
        int n = nb0 + ng * 8 + i;
        if (n >= NN) break;
        float h = g_has[n];
        float4 o0 = make_float4(acc[i][0].f2.x + h * bm0.x + br0.x,
                                acc[i][0].f2.y + h * bm0.y + br0.y,
                                acc[i][1].f2.x + h * bm0.z + br0.z,
                                acc[i][1].f2.y + h * bm0.w + br0.w);
        float4 o1 = make_float4(acc[i][2].f2.x + h * bm1.x + br1.x,
                                acc[i][2].f2.y + h * bm1.y + br1.y,
                                acc[i][3].f2.x + h * bm1.z + br1.z,
                                acc[i][3].f2.y + h * bm1.w + br1.w);
        float* op = out + (size_t)n * DD + cg * 8;
        *(float4*)op = o0;
        *(float4*)(op + 4) = o1;
    }
}

// ---------------- launcher ---------------------------------------------------
extern "C" void kernel_launch(void* const* d_in, const int* in_sizes, int n_in,
                              void* d_out, int out_size) {
    const float* x  = (const float*)d_in[0];
    const void*  ei = d_in[1];
    const float* Wm = (const float*)d_in[2];
    const float* bm = (const float*)d_in[3];
    const float* Wr = (const float*)d_in[4];
    const float* br = (const float*)d_in[5];
    float* out = (float*)d_out;

    k_detect<<<1, 256>>>((const unsigned*)ei);
    k_init<<<(NN + 255) / 256, 256>>>(Wm, bm);
    k_snode<<<(NN + 255) / 256, 256>>>(x);
    k_deg<<<(EE + 255) / 256, 256>>>(ei);
    k_scan<<<1, 1024>>>();
    k_scatter<<<(EE + 255) / 256, 256>>>();
    k_agg<<<(NN + 7) / 8, 256>>>(x);
    k_out<<<(NN + 255) / 256, 256>>>(x, Wm, bm, Wr, br, out);
}

// round 8
// speedup vs baseline: 2.1740x; 1.8707x over previous
#include <cuda_runtime.h>

#define NN 100000
#define EE 1600000
#define DD 64
#define SCAN_T 1024
#define SCAN_B ((NN + SCAN_T - 1) / SCAN_T)   // 98
#define EDGE_BLOCKS (EE / 256)                // 6250 (exact)
#define SN_BLOCKS ((NN + 255) / 256)          // 391

// ---------------- scratch (static device globals; no allocation) ------------
__device__ int      g_is64;
__device__ unsigned g_smaxkey;
__device__ float    g_smaxf;
__device__ float    g_snode[NN];
__device__ float    g_has[NN];
__device__ int      g_deg[NN];
__device__ int      g_off[NN + 1];
__device__ int      g_cur[NN];
__device__ int      g_row32[EE];
__device__ int      g_col32[EE];
__device__ int2     g_edge[EE];              // .x = srcRow, .y = bits(exp(s-gmax))
__device__ float    g_agg[(size_t)NN * DD];
__device__ unsigned long long g_scanstate[SCAN_B];  // (flag<<32)|value

// ---------------- packed f32x2 FMA (2x fp32 FMA rate on sm_103a) ------------
union F2U { float2 f2; unsigned long long u; };
__device__ __forceinline__ F2U ffma2(F2U a, F2U b, F2U c) {
    F2U d;
    asm("fma.rn.f32x2 %0, %1, %2, %3;" : "=l"(d.u) : "l"(a.u), "l"(b.u), "l"(c.u));
    return d;
}

// ---------------- K0: detect int64/int32 + zero deg + zero scan state -------
__global__ void __launch_bounds__(256) k_prep(const unsigned* __restrict__ ei32) {
    int t = blockIdx.x * blockDim.x + threadIdx.x;
    if (t < NN) g_deg[t] = 0;
    if (t < SCAN_B) g_scanstate[t] = 0ull;
    if (t == 0) g_smaxkey = 0u;
    if (blockIdx.x == 0) {
        // int64 little-endian non-negative ids => odd 32-bit words are all 0.
        __shared__ int any;
        if (threadIdx.x == 0) any = 0;
        __syncthreads();
        int v = 0;
        for (int i = threadIdx.x; i < 4096; i += blockDim.x) v |= (int)ei32[2 * i + 1];
        if (v) atomicOr(&any, 1);
        __syncthreads();
        if (threadIdx.x == 0) g_is64 = any ? 0 : 1;
    }
}

// ---------------- K1: FUSED  (edge conversion + histogram) || (node scores) -
__global__ void __launch_bounds__(256) k_fused(
    const float* __restrict__ x, const void* __restrict__ ei,
    const float* __restrict__ Wm, const float* __restrict__ bm) {
    int b = blockIdx.x;
    if (b < EDGE_BLOCKS) {
        int e = b * 256 + threadIdx.x;   // EDGE_BLOCKS*256 == EE exactly
        int row, col;
        if (g_is64) {
            row = (int)__ldg(&((const long long*)ei)[e]);
            col = (int)__ldg(&((const long long*)ei)[(long long)EE + e]);
        } else {
            row = __ldg(&((const int*)ei)[e]);
            col = __ldg(&((const int*)ei)[EE + e]);
        }
        g_row32[e] = row;
        g_col32[e] = col;
        atomicAdd(&g_deg[col], 1);
    } else {
        // per-node score s = x[n].wbar + bmean  (wbar computed per block, cheap)
        __shared__ float swb[DD];
        __shared__ float sbm;
        int t = threadIdx.x;
        if (t < DD) {
            float s = 0.f;
#pragma unroll
            for (int j = 0; j < DD; j++) s += __ldg(&Wm[t * DD + j]);
            swb[t] = s * (1.0f / DD);
        }
        if (t == 0) {
            float bs = 0.f;
            for (int j = 0; j < DD; j++) bs += __ldg(&bm[j]);
            sbm = bs * (1.0f / DD);
        }
        __syncthreads();
        int n = (b - EDGE_BLOCKS) * 256 + t;
        float s = -1e30f;
        if (n < NN) {
            const float4* xp = (const float4*)(x + (size_t)n * DD);
            float acc = 0.f;
#pragma unroll
            for (int i = 0; i < DD / 4; i++) {
                float4 v = __ldg(&xp[i]);
                acc += v.x * swb[4 * i] + v.y * swb[4 * i + 1] +
                       v.z * swb[4 * i + 2] + v.w * swb[4 * i + 3];
            }
            s = acc + sbm;  // BETA = 1.0
            g_snode[n] = s;
        }
        float m = s;
#pragma unroll
        for (int o = 16; o; o >>= 1) m = fmaxf(m, __shfl_xor_sync(0xffffffffu, m, o));
        if ((t & 31) == 0) {
            unsigned bb = __float_as_uint(m);
            unsigned key = (bb & 0x80000000u) ? ~bb : (bb | 0x80000000u);
            atomicMax(&g_smaxkey, key);
        }
    }
}

// ---------------- K2: decoupled-lookback exclusive scan (one launch) --------
__global__ void __launch_bounds__(SCAN_T) k_scan() {
    int b = blockIdx.x, t = threadIdx.x;
    int i = b * SCAN_T + t;
    int v = (i < NN) ? g_deg[i] : 0;

    int lane = t & 31, wid = t >> 5;
    int inc = v;
#pragma unroll
    for (int o = 1; o < 32; o <<= 1) {
        int u = __shfl_up_sync(0xffffffffu, inc, o);
        if (lane >= o) inc += u;
    }
    __shared__ int wtot[32];
    __shared__ int stotal;
    __shared__ int sprefix;
    if (lane == 31) wtot[wid] = inc;
    __syncthreads();
    if (wid == 0) {
        int s = wtot[lane];
        int sinc = s;
#pragma unroll
        for (int o = 1; o < 32; o <<= 1) {
            int u = __shfl_up_sync(0xffffffffu, sinc, o);
            if (lane >= o) sinc += u;
        }
        wtot[lane] = sinc - s;          // exclusive warp base
        if (lane == 31) stotal = sinc;  // block total
    }
    __syncthreads();
    int ex = wtot[wid] + inc - v;       // block-local exclusive prefix
    int total = stotal;

    if (t == 0) {
        if (b == 0) {
            atomicExch(&g_scanstate[0], (2ull << 32) | (unsigned)total);
            sprefix = 0;
            // decode global max while we're the first block
            unsigned k = g_smaxkey;
            unsigned bb = (k & 0x80000000u) ? (k ^ 0x80000000u) : ~k;
            g_smaxf = __uint_as_float(bb);
        } else {
            atomicExch(&g_scanstate[b], (1ull << 32) | (unsigned)total);
            int prefix = 0;
            for (int j = b - 1; j >= 0;) {
                unsigned long long st;
                do { st = atomicAdd(&g_scanstate[j], 0ull); } while ((st >> 32) == 0ull);
                prefix += (int)(unsigned)st;
                if ((st >> 32) == 2ull) break;
                j--;
            }
            atomicExch(&g_scanstate[b], (2ull << 32) | (unsigned)(prefix + total));
            sprefix = prefix;
        }
        if (b == SCAN_B - 1) g_off[NN] = 0;  // placeholder, overwritten below
    }
    __syncthreads();
    int off = sprefix + ex;
    if (i < NN) { g_off[i] = off; g_cur[i] = off; }
    if (b == SCAN_B - 1 && t == 0) g_off[NN] = sprefix + total;  // == EE
}

// ---------------- K3: scatter (row, exp-weight) into CSR-by-dest ------------
__global__ void __launch_bounds__(256) k_scatter() {
    int e = blockIdx.x * 256 + threadIdx.x;  // grid covers EE exactly
    int row = g_row32[e];
    int col = g_col32[e];
    float w = __expf(g_snode[row] - g_smaxf);
    int pos = atomicAdd(&g_cur[col], 1);
    g_edge[pos] = make_int2(row, __float_as_int(w));
}

// ---------------- K4: warp-per-node weighted aggregation (single pass) ------
__global__ void __launch_bounds__(256) k_agg(const float* __restrict__ x) {
    int warp = (blockIdx.x * blockDim.x + threadIdx.x) >> 5;
    int lane = threadIdx.x & 31;
    if (warp >= NN) return;
    int n = warp;
    int beg = g_off[n], end = g_off[n + 1];

    int half = lane >> 4;   // edge slot (2 per iteration)
    int q = lane & 15;      // dim quarter (float4)
    float4 acc = make_float4(0.f, 0.f, 0.f, 0.f);
    float sumw = 0.f;
#pragma unroll 4
    for (int i = beg + half; i < end; i += 2) {
        int2 ed = __ldg(&g_edge[i]);
        float w = __int_as_float(ed.y);
        if (q == 0) sumw += w;
        const float4* xp = (const float4*)(x + (size_t)ed.x * DD);
        float4 v = __ldg(&xp[q]);
        acc.x += w * v.x; acc.y += w * v.y; acc.z += w * v.z; acc.w += w * v.w;
    }
    acc.x += __shfl_xor_sync(0xffffffffu, acc.x, 16);
    acc.y += __shfl_xor_sync(0xffffffffu, acc.y, 16);
    acc.z += __shfl_xor_sync(0xffffffffu, acc.z, 16);
    acc.w += __shfl_xor_sync(0xffffffffu, acc.w, 16);
#pragma unroll
    for (int o = 16; o; o >>= 1) sumw += __shfl_xor_sync(0xffffffffu, sumw, o);

    float inv = (sumw > 0.f) ? (1.0f / sumw) : 0.f;
    if (half == 0) {
        float4 r = make_float4(acc.x * inv, acc.y * inv, acc.z * inv, acc.w * inv);
        ((float4*)(g_agg + (size_t)n * DD))[q] = r;
    }
    if (lane == 0) g_has[n] = (sumw > 0.f) ? 1.0f : 0.0f;
}

// ---------------- K5: out = agg@Wm + has*bm + x@Wr + br ---------------------
// 256 nodes x 64 cols per block; thread = 8 nodes x 8 cols, f32x2 FMAs.
#define SA_STRIDE 260
__global__ void __launch_bounds__(256, 1) k_out(
    const float* __restrict__ x,
    const float* __restrict__ Wm, const float* __restrict__ bm,
    const float* __restrict__ Wr, const float* __restrict__ br,
    float* __restrict__ out) {
    __shared__ float sAk[32 * SA_STRIDE];  // [k within chunk][node]
    __shared__ float sWs[32 * 64];         // [k within chunk][col]

    int t = threadIdx.x;
    int cg = t & 7;
    int ng = t >> 3;
    int nb0 = blockIdx.x * 256;

    float4 bm0 = __ldg((const float4*)(bm + cg * 8));
    float4 bm1 = __ldg((const float4*)(bm + cg * 8 + 4));
    float4 br0 = __ldg((const float4*)(br + cg * 8));
    float4 br1 = __ldg((const float4*)(br + cg * 8 + 4));

    F2U acc[8][4];
#pragma unroll
    for (int i = 0; i < 8; i++)
#pragma unroll
        for (int p = 0; p < 4; p++) acc[i][p].u = 0ull;

    int node = nb0 + t;
    for (int kc = 0; kc < 4; kc++) {
        const float* Asrc = (kc < 2) ? g_agg : x;
        int koff = (kc < 2) ? kc * 32 : (kc - 2) * 32;
        const float* Wsrc = (kc < 2) ? (Wm + kc * 32 * 64) : (Wr + (kc - 2) * 32 * 64);
        __syncthreads();
        const float4* ap = (const float4*)(Asrc + (size_t)node * DD + koff);
#pragma unroll
        for (int kq = 0; kq < 8; kq++) {
            float4 v = (node < NN) ? __ldg(&ap[kq]) : make_float4(0.f, 0.f, 0.f, 0.f);
            sAk[(kq * 4 + 0) * SA_STRIDE + t] = v.x;
            sAk[(kq * 4 + 1) * SA_STRIDE + t] = v.y;
            sAk[(kq * 4 + 2) * SA_STRIDE + t] = v.z;
            sAk[(kq * 4 + 3) * SA_STRIDE + t] = v.w;
        }
        ((float4*)sWs)[t] = __ldg(&((const float4*)Wsrc)[t]);
        ((float4*)sWs)[t + 256] = __ldg(&((const float4*)Wsrc)[t + 256]);
        __syncthreads();

#pragma unroll 4
        for (int kk = 0; kk < 32; kk++) {
            float4 wa = *(const float4*)&sWs[kk * 64 + cg * 8];
            float4 wb = *(const float4*)&sWs[kk * 64 + cg * 8 + 4];
            F2U w0, w1, w2, w3;
            w0.f2 = make_float2(wa.x, wa.y); w1.f2 = make_float2(wa.z, wa.w);
            w2.f2 = make_float2(wb.x, wb.y); w3.f2 = make_float2(wb.z, wb.w);
            float4 a03 = *(const float4*)&sAk[kk * SA_STRIDE + ng * 8];
            float4 a47 = *(const float4*)&sAk[kk * SA_STRIDE + ng * 8 + 4];
            float av[8] = {a03.x, a03.y, a03.z, a03.w, a47.x, a47.y, a47.z, a47.w};
#pragma unroll
            for (int i = 0; i < 8; i++) {
                F2U ap2; ap2.f2 = make_float2(av[i], av[i]);
                acc[i][0] = ffma2(ap2, w0, acc[i][0]);
                acc[i][1] = ffma2(ap2, w1, acc[i][1]);
                acc[i][2] = ffma2(ap2, w2, acc[i][2]);
                acc[i][3] = ffma2(ap2, w3, acc[i][3]);
            }
        }
    }

#pragma unroll
    for (int i = 0; i < 8; i++) {
        int n = nb0 + ng * 8 + i;
        if (n >= NN) break;
        float h = g_has[n];
        float4 o0 = make_float4(acc[i][0].f2.x + h * bm0.x + br0.x,
                                acc[i][0].f2.y + h * bm0.y + br0.y,
                                acc[i][1].f2.x + h * bm0.z + br0.z,
                                acc[i][1].f2.y + h * bm0.w + br0.w);
        float4 o1 = make_float4(acc[i][2].f2.x + h * bm1.x + br1.x,
                                acc[i][2].f2.y + h * bm1.y + br1.y,
                                acc[i][3].f2.x + h * bm1.z + br1.z,
                                acc[i][3].f2.y + h * bm1.w + br1.w);
        float* op = out + (size_t)n * DD + cg * 8;
        *(float4*)op = o0;
        *(float4*)(op + 4) = o1;
    }
}

// ---------------- launcher ---------------------------------------------------
extern "C" void kernel_launch(void* const* d_in, const int* in_sizes, int n_in,
                              void* d_out, int out_size) {
    const float* x  = (const float*)d_in[0];
    const void*  ei = d_in[1];
    const float* Wm = (const float*)d_in[2];
    const float* bm = (const float*)d_in[3];
    const float* Wr = (const float*)d_in[4];
    const float* br = (const float*)d_in[5];
    float* out = (float*)d_out;

    k_prep<<<SN_BLOCKS, 256>>>((const unsigned*)ei);
    k_fused<<<EDGE_BLOCKS + SN_BLOCKS, 256>>>(x, ei, Wm, bm);
    k_scan<<<SCAN_B, SCAN_T>>>();
    k_scatter<<<EDGE_BLOCKS, 256>>>();
    k_agg<<<(NN + 7) / 8, 256>>>(x);
    k_out<<<(NN + 255) / 256, 256>>>(x, Wm, bm, Wr, br, out);
}